// round 1
// baseline (speedup 1.0000x reference)
#include <cuda_runtime.h>

#define NN 100000
#define NE 1600000
#define C  128

// Scratch (device globals: no allocation allowed in kernel_launch)
__device__ float g_deg [NN];
__device__ float g_dinv[NN];
__device__ float g_h   [(size_t)NN * C];   // x@W1 (stage1 pre-aggregation)
__device__ float g_agg1[(size_t)NN * C];   // stage1 aggregate -> normalized hidden
__device__ float g_agg2[(size_t)NN * C];   // stage2 aggregate of hidden

// ---------------------------------------------------------------------------
// init: deg=1 (self-loop), zero both aggregation buffers
// ---------------------------------------------------------------------------
__global__ void init_kernel() {
    int tid    = blockIdx.x * blockDim.x + threadIdx.x;
    int stride = gridDim.x * blockDim.x;
    const int nq = NN * C / 4;  // float4 count per buffer
    float4 z = make_float4(0.f, 0.f, 0.f, 0.f);
    for (int i = tid; i < nq; i += stride) {
        reinterpret_cast<float4*>(g_agg1)[i] = z;
        reinterpret_cast<float4*>(g_agg2)[i] = z;
    }
    for (int i = tid; i < NN; i += stride) g_deg[i] = 1.0f;
}

// ---------------------------------------------------------------------------
// degree accumulation over dst
// ---------------------------------------------------------------------------
__global__ void deg_kernel(const int* __restrict__ dst) {
    int e = blockIdx.x * blockDim.x + threadIdx.x;
    if (e < NE) atomicAdd(&g_deg[dst[e]], 1.0f);
}

__global__ void dinv_kernel() {
    int i = blockIdx.x * blockDim.x + threadIdx.x;
    if (i < NN) g_dinv[i] = rsqrtf(g_deg[i]);   // deg >= 1 always (self-loop)
}

// ---------------------------------------------------------------------------
// GEMM1: g_h = X @ W   (X: [n,128], W: [128,128])
// 128 rows/block, 256 threads, 8x8 register micro-tile per thread
// ---------------------------------------------------------------------------
__global__ __launch_bounds__(256, 2)
void gemm1_kernel(const float* __restrict__ X, const float* __restrict__ W, int nrows) {
    __shared__ float ws [32][128];
    __shared__ float xsT[32][136];   // transposed x-tile, padded (136*4 % 16 == 0)

    const int tid   = threadIdx.x;
    const int tx    = tid & 15;      // output column group (8 cols)
    const int ty    = tid >> 4;      // output row group    (8 rows)
    const int rbase = blockIdx.x * 128;

    float acc[8][8];
#pragma unroll
    for (int i = 0; i < 8; i++)
#pragma unroll
        for (int j = 0; j < 8; j++) acc[i][j] = 0.f;

    for (int kc = 0; kc < 128; kc += 32) {
#pragma unroll
        for (int l = 0; l < 4; l++) {            // W tile: 32x128
            int idx = tid + l * 256;
            int k = idx >> 5, j4 = idx & 31;
            *reinterpret_cast<float4*>(&ws[k][j4 * 4]) =
                *reinterpret_cast<const float4*>(&W[(kc + k) * C + j4 * 4]);
        }
#pragma unroll
        for (int l = 0; l < 4; l++) {            // X tile (transposed): 128 rows x 32 k
            int idx = tid + l * 256;
            int r = idx >> 3, kq = idx & 7;
            float4 v = make_float4(0.f, 0.f, 0.f, 0.f);
            if (rbase + r < nrows)
                v = *reinterpret_cast<const float4*>(&X[(size_t)(rbase + r) * C + kc + kq * 4]);
            xsT[kq * 4 + 0][r] = v.x;
            xsT[kq * 4 + 1][r] = v.y;
            xsT[kq * 4 + 2][r] = v.z;
            xsT[kq * 4 + 3][r] = v.w;
        }
        __syncthreads();
#pragma unroll 8
        for (int k = 0; k < 32; k++) {
            float xv[8], wv[8];
            *reinterpret_cast<float4*>(&xv[0]) = *reinterpret_cast<float4*>(&xsT[k][ty * 8]);
            *reinterpret_cast<float4*>(&xv[4]) = *reinterpret_cast<float4*>(&xsT[k][ty * 8 + 4]);
            *reinterpret_cast<float4*>(&wv[0]) = *reinterpret_cast<float4*>(&ws[k][tx * 8]);
            *reinterpret_cast<float4*>(&wv[4]) = *reinterpret_cast<float4*>(&ws[k][tx * 8 + 4]);
#pragma unroll
            for (int i = 0; i < 8; i++)
#pragma unroll
                for (int j = 0; j < 8; j++)
                    acc[i][j] = fmaf(xv[i], wv[j], acc[i][j]);
        }
        __syncthreads();
    }
#pragma unroll
    for (int i = 0; i < 8; i++) {
        int r = rbase + ty * 8 + i;
        if (r < nrows) {
            *reinterpret_cast<float4*>(&g_h[(size_t)r * C + tx * 8]) =
                make_float4(acc[i][0], acc[i][1], acc[i][2], acc[i][3]);
            *reinterpret_cast<float4*>(&g_h[(size_t)r * C + tx * 8 + 4]) =
                make_float4(acc[i][4], acc[i][5], acc[i][6], acc[i][7]);
        }
    }
}

// ---------------------------------------------------------------------------
// Edge aggregation: one warp per edge, 128 channels = 32 lanes x float4
// agg[dst] += h[src] * dinv[src]*dinv[dst]   (vector atomics)
// STAGE 0: g_h -> g_agg1;  STAGE 1: g_agg1 -> g_agg2
// ---------------------------------------------------------------------------
template <int STAGE>
__global__ __launch_bounds__(256)
void edge_agg_kernel(const int* __restrict__ src, const int* __restrict__ dst) {
    int e    = (blockIdx.x * blockDim.x + threadIdx.x) >> 5;
    int lane = threadIdx.x & 31;
    if (e >= NE) return;
    int s = src[e];
    int d = dst[e];
    float c = g_dinv[s] * g_dinv[d];
    const float* hsrc = (STAGE == 0) ? g_h : g_agg1;
    float*       agg  = (STAGE == 0) ? g_agg1 : g_agg2;
    float4 v = *reinterpret_cast<const float4*>(&hsrc[(size_t)s * C + lane * 4]);
    float* p = &agg[(size_t)d * C + lane * 4];
    asm volatile("red.global.add.v4.f32 [%0], {%1, %2, %3, %4};"
                 :: "l"(p), "f"(v.x * c), "f"(v.y * c), "f"(v.z * c), "f"(v.w * c)
                 : "memory");
}

// ---------------------------------------------------------------------------
// post1: add self-loop + bias, relu, L2-normalize row  (in-place in g_agg1)
// one warp per node
// ---------------------------------------------------------------------------
__global__ __launch_bounds__(256)
void post1_kernel(const float* __restrict__ b1) {
    int node = (blockIdx.x * blockDim.x + threadIdx.x) >> 5;
    int lane = threadIdx.x & 31;
    if (node >= NN) return;
    float dv = g_dinv[node];
    float cc = dv * dv;
    size_t base = (size_t)node * C + lane * 4;
    float4 a  = *reinterpret_cast<const float4*>(&g_agg1[base]);
    float4 hv = *reinterpret_cast<const float4*>(&g_h[base]);
    float4 bv = *reinterpret_cast<const float4*>(&b1[lane * 4]);
    float4 v;
    v.x = fmaxf(fmaf(hv.x, cc, a.x) + bv.x, 0.f);
    v.y = fmaxf(fmaf(hv.y, cc, a.y) + bv.y, 0.f);
    v.z = fmaxf(fmaf(hv.z, cc, a.z) + bv.z, 0.f);
    v.w = fmaxf(fmaf(hv.w, cc, a.w) + bv.w, 0.f);
    float ss = v.x * v.x + v.y * v.y + v.z * v.z + v.w * v.w;
#pragma unroll
    for (int off = 16; off > 0; off >>= 1)
        ss += __shfl_xor_sync(0xffffffffu, ss, off);
    float scale = 1.0f / fmaxf(sqrtf(ss), 1e-12f);
    v.x *= scale; v.y *= scale; v.z *= scale; v.w *= scale;
    *reinterpret_cast<float4*>(&g_agg1[base]) = v;
}

// ---------------------------------------------------------------------------
// Final: v = g_agg2 + g_agg1*dinv^2 (self loop), then
//   mu     = v @ Wmu + bmu  -> out[0        : NN*64]
//   logstd = v @ Wls + bls  -> out[NN*64    : 2*NN*64]
// Same GEMM structure with [Wmu|Wls] packed into the 128-wide ws tile.
// ---------------------------------------------------------------------------
__global__ __launch_bounds__(256, 2)
void gemm_final_kernel(const float* __restrict__ Wmu, const float* __restrict__ Wls,
                       const float* __restrict__ bmu, const float* __restrict__ bls,
                       float* __restrict__ out, int nrows) {
    __shared__ float ws [32][128];
    __shared__ float xsT[32][136];

    const int tid   = threadIdx.x;
    const int tx    = tid & 15;
    const int ty    = tid >> 4;
    const int rbase = blockIdx.x * 128;

    float acc[8][8];
#pragma unroll
    for (int i = 0; i < 8; i++)
#pragma unroll
        for (int j = 0; j < 8; j++) acc[i][j] = 0.f;

    for (int kc = 0; kc < 128; kc += 32) {
#pragma unroll
        for (int l = 0; l < 4; l++) {      // packed [Wmu | Wls] tile
            int idx = tid + l * 256;
            int k = idx >> 5, j4 = idx & 31;
            int j = j4 * 4;
            float4 wv;
            if (j < 64) wv = *reinterpret_cast<const float4*>(&Wmu[(kc + k) * 64 + j]);
            else        wv = *reinterpret_cast<const float4*>(&Wls[(kc + k) * 64 + j - 64]);
            *reinterpret_cast<float4*>(&ws[k][j]) = wv;
        }
#pragma unroll
        for (int l = 0; l < 4; l++) {      // v tile = agg2 + hn*dinv^2, transposed
            int idx = tid + l * 256;
            int r = idx >> 3, kq = idx & 7;
            float4 v = make_float4(0.f, 0.f, 0.f, 0.f);
            if (rbase + r < nrows) {
                float dv = g_dinv[rbase + r];
                float cc = dv * dv;
                size_t base = (size_t)(rbase + r) * C + kc + kq * 4;
                float4 a = *reinterpret_cast<const float4*>(&g_agg2[base]);
                float4 h = *reinterpret_cast<const float4*>(&g_agg1[base]);
                v.x = fmaf(h.x, cc, a.x);
                v.y = fmaf(h.y, cc, a.y);
                v.z = fmaf(h.z, cc, a.z);
                v.w = fmaf(h.w, cc, a.w);
            }
            xsT[kq * 4 + 0][r] = v.x;
            xsT[kq * 4 + 1][r] = v.y;
            xsT[kq * 4 + 2][r] = v.z;
            xsT[kq * 4 + 3][r] = v.w;
        }
        __syncthreads();
#pragma unroll 8
        for (int k = 0; k < 32; k++) {
            float xv[8], wv[8];
            *reinterpret_cast<float4*>(&xv[0]) = *reinterpret_cast<float4*>(&xsT[k][ty * 8]);
            *reinterpret_cast<float4*>(&xv[4]) = *reinterpret_cast<float4*>(&xsT[k][ty * 8 + 4]);
            *reinterpret_cast<float4*>(&wv[0]) = *reinterpret_cast<float4*>(&ws[k][tx * 8]);
            *reinterpret_cast<float4*>(&wv[4]) = *reinterpret_cast<float4*>(&ws[k][tx * 8 + 4]);
#pragma unroll
            for (int i = 0; i < 8; i++)
#pragma unroll
                for (int j = 0; j < 8; j++)
                    acc[i][j] = fmaf(xv[i], wv[j], acc[i][j]);
        }
        __syncthreads();
    }

    float bias[8];
    {
        const float* bp = (tx < 8) ? (bmu + tx * 8) : (bls + (tx - 8) * 8);
        *reinterpret_cast<float4*>(&bias[0]) = *reinterpret_cast<const float4*>(&bp[0]);
        *reinterpret_cast<float4*>(&bias[4]) = *reinterpret_cast<const float4*>(&bp[4]);
    }
    const size_t obase = (tx < 8) ? (size_t)0 : (size_t)NN * 64;
    const int    jo    = (tx < 8) ? tx * 8 : (tx - 8) * 8;
#pragma unroll
    for (int i = 0; i < 8; i++) {
        int r = rbase + ty * 8 + i;
        if (r < nrows) {
            float* op = out + obase + (size_t)r * 64 + jo;
            *reinterpret_cast<float4*>(op) =
                make_float4(acc[i][0] + bias[0], acc[i][1] + bias[1],
                            acc[i][2] + bias[2], acc[i][3] + bias[3]);
            *reinterpret_cast<float4*>(op + 4) =
                make_float4(acc[i][4] + bias[4], acc[i][5] + bias[5],
                            acc[i][6] + bias[6], acc[i][7] + bias[7]);
        }
    }
}

// ---------------------------------------------------------------------------
extern "C" void kernel_launch(void* const* d_in, const int* in_sizes, int n_in,
                              void* d_out, int out_size) {
    const float* x   = (const float*)d_in[0];
    const int*   ei  = (const int*)  d_in[1];
    const float* W1  = (const float*)d_in[2];
    const float* b1  = (const float*)d_in[3];
    const float* Wmu = (const float*)d_in[4];
    const float* bmu = (const float*)d_in[5];
    const float* Wls = (const float*)d_in[6];
    const float* bls = (const float*)d_in[7];
    float* out = (float*)d_out;

    const int* src = ei;        // edge_index[0]
    const int* dst = ei + NE;   // edge_index[1]

    const int gemm_blocks = (NN + 127) / 128;        // 782
    const int edge_blocks = (NE * 32 + 255) / 256;   // 200000 (warp/edge)

    init_kernel<<<12800, 256>>>();
    deg_kernel<<<(NE + 255) / 256, 256>>>(dst);
    dinv_kernel<<<(NN + 255) / 256, 256>>>();
    gemm1_kernel<<<gemm_blocks, 256>>>(x, W1, NN);
    edge_agg_kernel<0><<<edge_blocks, 256>>>(src, dst);
    post1_kernel<<<(NN * 32 + 255) / 256, 256>>>(b1);
    edge_agg_kernel<1><<<edge_blocks, 256>>>(src, dst);
    gemm_final_kernel<<<gemm_blocks, 256>>>(Wmu, Wls, bmu, bls, out, NN);
}

// round 2
// speedup vs baseline: 1.8453x; 1.8453x over previous
#include <cuda_runtime.h>

#define NN 100000
#define NE 1600000
#define C  128

#define SCAN_CHUNK 1024
#define NBLK_SCAN ((NN + SCAN_CHUNK - 1) / SCAN_CHUNK)   // 98

// Scratch (device globals — no allocation allowed)
__device__ int   g_cnt [NN];        // in-degree counts, then reused as fill cursor
__device__ int   g_off [NN + 1];    // CSR row offsets
__device__ int   g_bsum[SCAN_CHUNK];// block sums for 2-level scan
__device__ int   g_csrc[NE];        // CSR column (src) indices, grouped by dst
__device__ float g_dinv[NN];
__device__ float g_h   [(size_t)NN * C];  // x@W1
__device__ float g_hn  [(size_t)NN * C];  // normalized hidden (post layer-1)
__device__ float g_agg2[(size_t)NN * C];  // stage-2 aggregate (self incl.)

// ---------------------------------------------------------------------------
// CSR build: zero counts -> count -> scan(3) -> fill
// ---------------------------------------------------------------------------
__global__ void zero_cnt_kernel() {
    int i = blockIdx.x * blockDim.x + threadIdx.x;
    if (i < NN) g_cnt[i] = 0;
}

__global__ void count_kernel(const int* __restrict__ dst) {
    int e = blockIdx.x * blockDim.x + threadIdx.x;
    if (e < NE) atomicAdd(&g_cnt[dst[e]], 1);
}

// per-block inclusive scan over 1024-elem chunks; writes partial exclusive offsets
__global__ __launch_bounds__(SCAN_CHUNK)
void scan1_kernel() {
    __shared__ int sh[SCAN_CHUNK];
    int i = blockIdx.x * SCAN_CHUNK + threadIdx.x;
    int v = (i < NN) ? g_cnt[i] : 0;
    sh[threadIdx.x] = v;
    __syncthreads();
#pragma unroll
    for (int off = 1; off < SCAN_CHUNK; off <<= 1) {
        int t = (threadIdx.x >= off) ? sh[threadIdx.x - off] : 0;
        __syncthreads();
        sh[threadIdx.x] += t;
        __syncthreads();
    }
    if (i < NN) g_off[i] = sh[threadIdx.x] - v;   // exclusive within block
    if (threadIdx.x == SCAN_CHUNK - 1) g_bsum[blockIdx.x] = sh[SCAN_CHUNK - 1];
}

// single-block exclusive scan of the 98 block sums
__global__ __launch_bounds__(128)
void scan2_kernel() {
    __shared__ int sh[128];
    int v = (threadIdx.x < NBLK_SCAN) ? g_bsum[threadIdx.x] : 0;
    sh[threadIdx.x] = v;
    __syncthreads();
#pragma unroll
    for (int off = 1; off < 128; off <<= 1) {
        int t = (threadIdx.x >= off) ? sh[threadIdx.x - off] : 0;
        __syncthreads();
        sh[threadIdx.x] += t;
        __syncthreads();
    }
    if (threadIdx.x < NBLK_SCAN) g_bsum[threadIdx.x] = sh[threadIdx.x] - v;
}

// add block offsets, compute dinv, reset cursor, set sentinel
__global__ __launch_bounds__(SCAN_CHUNK)
void scan3_kernel() {
    int i = blockIdx.x * SCAN_CHUNK + threadIdx.x;
    if (i < NN) {
        g_off[i] += g_bsum[blockIdx.x];
        g_dinv[i] = rsqrtf((float)g_cnt[i] + 1.0f);   // +1 self-loop
        g_cnt[i] = 0;                                  // reuse as fill cursor
    }
    if (i == 0) g_off[NN] = NE;
}

__global__ void fill_kernel(const int* __restrict__ src, const int* __restrict__ dst) {
    int e = blockIdx.x * blockDim.x + threadIdx.x;
    if (e < NE) {
        int d = dst[e];
        int p = atomicAdd(&g_cnt[d], 1);
        g_csrc[g_off[d] + p] = src[e];
    }
}

// ---------------------------------------------------------------------------
// GEMM1: g_h = X @ W   (X: [n,128], W: [128,128]) — 8x8 micro-tile, FFMA roofline
// ---------------------------------------------------------------------------
__global__ __launch_bounds__(256, 2)
void gemm1_kernel(const float* __restrict__ X, const float* __restrict__ W, int nrows) {
    __shared__ float ws [32][128];
    __shared__ float xsT[32][136];

    const int tid   = threadIdx.x;
    const int tx    = tid & 15;
    const int ty    = tid >> 4;
    const int rbase = blockIdx.x * 128;

    float acc[8][8];
#pragma unroll
    for (int i = 0; i < 8; i++)
#pragma unroll
        for (int j = 0; j < 8; j++) acc[i][j] = 0.f;

    for (int kc = 0; kc < 128; kc += 32) {
#pragma unroll
        for (int l = 0; l < 4; l++) {
            int idx = tid + l * 256;
            int k = idx >> 5, j4 = idx & 31;
            *reinterpret_cast<float4*>(&ws[k][j4 * 4]) =
                *reinterpret_cast<const float4*>(&W[(kc + k) * C + j4 * 4]);
        }
#pragma unroll
        for (int l = 0; l < 4; l++) {
            int idx = tid + l * 256;
            int r = idx >> 3, kq = idx & 7;
            float4 v = make_float4(0.f, 0.f, 0.f, 0.f);
            if (rbase + r < nrows)
                v = *reinterpret_cast<const float4*>(&X[(size_t)(rbase + r) * C + kc + kq * 4]);
            xsT[kq * 4 + 0][r] = v.x;
            xsT[kq * 4 + 1][r] = v.y;
            xsT[kq * 4 + 2][r] = v.z;
            xsT[kq * 4 + 3][r] = v.w;
        }
        __syncthreads();
#pragma unroll 8
        for (int k = 0; k < 32; k++) {
            float xv[8], wv[8];
            *reinterpret_cast<float4*>(&xv[0]) = *reinterpret_cast<float4*>(&xsT[k][ty * 8]);
            *reinterpret_cast<float4*>(&xv[4]) = *reinterpret_cast<float4*>(&xsT[k][ty * 8 + 4]);
            *reinterpret_cast<float4*>(&wv[0]) = *reinterpret_cast<float4*>(&ws[k][tx * 8]);
            *reinterpret_cast<float4*>(&wv[4]) = *reinterpret_cast<float4*>(&ws[k][tx * 8 + 4]);
#pragma unroll
            for (int i = 0; i < 8; i++)
#pragma unroll
                for (int j = 0; j < 8; j++)
                    acc[i][j] = fmaf(xv[i], wv[j], acc[i][j]);
        }
        __syncthreads();
    }
#pragma unroll
    for (int i = 0; i < 8; i++) {
        int r = rbase + ty * 8 + i;
        if (r < nrows) {
            *reinterpret_cast<float4*>(&g_h[(size_t)r * C + tx * 8]) =
                make_float4(acc[i][0], acc[i][1], acc[i][2], acc[i][3]);
            *reinterpret_cast<float4*>(&g_h[(size_t)r * C + tx * 8 + 4]) =
                make_float4(acc[i][4], acc[i][5], acc[i][6], acc[i][7]);
        }
    }
}

// ---------------------------------------------------------------------------
// CSR gather: one warp per node, lane owns 4 channels.
// acc = dinv[n]^2 * H[n] + sum_e dinv[src]*dinv[n] * H[src]
// STAGE 0: H=g_h,  epilogue = +bias, relu, L2-normalize -> g_hn
// STAGE 1: H=g_hn, plain store -> g_agg2
// ---------------------------------------------------------------------------
template <int STAGE>
__global__ __launch_bounds__(256)
void gather_kernel(const float* __restrict__ b1) {
    int node = (blockIdx.x * blockDim.x + threadIdx.x) >> 5;
    int lane = threadIdx.x & 31;
    if (node >= NN) return;

    const float* __restrict__ H = (STAGE == 0) ? g_h : g_hn;
    const size_t cb = (size_t)lane * 4;
    const float dn = g_dinv[node];

    float4 hv = *reinterpret_cast<const float4*>(&H[(size_t)node * C + cb]);
    float cc = dn * dn;
    float4 acc = make_float4(hv.x * cc, hv.y * cc, hv.z * cc, hv.w * cc);

    int e   = g_off[node];
    int end = g_off[node + 1];

    for (; e + 4 <= end; e += 4) {
        int s0 = g_csrc[e + 0], s1 = g_csrc[e + 1];
        int s2 = g_csrc[e + 2], s3 = g_csrc[e + 3];
        float c0 = g_dinv[s0] * dn, c1 = g_dinv[s1] * dn;
        float c2 = g_dinv[s2] * dn, c3 = g_dinv[s3] * dn;
        float4 v0 = *reinterpret_cast<const float4*>(&H[(size_t)s0 * C + cb]);
        float4 v1 = *reinterpret_cast<const float4*>(&H[(size_t)s1 * C + cb]);
        float4 v2 = *reinterpret_cast<const float4*>(&H[(size_t)s2 * C + cb]);
        float4 v3 = *reinterpret_cast<const float4*>(&H[(size_t)s3 * C + cb]);
        acc.x = fmaf(c0, v0.x, fmaf(c1, v1.x, fmaf(c2, v2.x, fmaf(c3, v3.x, acc.x))));
        acc.y = fmaf(c0, v0.y, fmaf(c1, v1.y, fmaf(c2, v2.y, fmaf(c3, v3.y, acc.y))));
        acc.z = fmaf(c0, v0.z, fmaf(c1, v1.z, fmaf(c2, v2.z, fmaf(c3, v3.z, acc.z))));
        acc.w = fmaf(c0, v0.w, fmaf(c1, v1.w, fmaf(c2, v2.w, fmaf(c3, v3.w, acc.w))));
    }
    for (; e < end; e++) {
        int s = g_csrc[e];
        float c = g_dinv[s] * dn;
        float4 v = *reinterpret_cast<const float4*>(&H[(size_t)s * C + cb]);
        acc.x = fmaf(c, v.x, acc.x);
        acc.y = fmaf(c, v.y, acc.y);
        acc.z = fmaf(c, v.z, acc.z);
        acc.w = fmaf(c, v.w, acc.w);
    }

    if (STAGE == 0) {
        float4 bv = *reinterpret_cast<const float4*>(&b1[lane * 4]);
        acc.x = fmaxf(acc.x + bv.x, 0.f);
        acc.y = fmaxf(acc.y + bv.y, 0.f);
        acc.z = fmaxf(acc.z + bv.z, 0.f);
        acc.w = fmaxf(acc.w + bv.w, 0.f);
        float ss = acc.x * acc.x + acc.y * acc.y + acc.z * acc.z + acc.w * acc.w;
#pragma unroll
        for (int off = 16; off > 0; off >>= 1)
            ss += __shfl_xor_sync(0xffffffffu, ss, off);
        float scale = 1.0f / fmaxf(sqrtf(ss), 1e-12f);
        acc.x *= scale; acc.y *= scale; acc.z *= scale; acc.w *= scale;
        *reinterpret_cast<float4*>(&g_hn[(size_t)node * C + cb]) = acc;
    } else {
        *reinterpret_cast<float4*>(&g_agg2[(size_t)node * C + cb]) = acc;
    }
}

// ---------------------------------------------------------------------------
// Final fused GEMM: [mu | logstd] = g_agg2 @ [Wmu | Wls] + [bmu | bls]
// ---------------------------------------------------------------------------
__global__ __launch_bounds__(256, 2)
void gemm_final_kernel(const float* __restrict__ Wmu, const float* __restrict__ Wls,
                       const float* __restrict__ bmu, const float* __restrict__ bls,
                       float* __restrict__ out, int nrows) {
    __shared__ float ws [32][128];
    __shared__ float xsT[32][136];

    const int tid   = threadIdx.x;
    const int tx    = tid & 15;
    const int ty    = tid >> 4;
    const int rbase = blockIdx.x * 128;

    float acc[8][8];
#pragma unroll
    for (int i = 0; i < 8; i++)
#pragma unroll
        for (int j = 0; j < 8; j++) acc[i][j] = 0.f;

    for (int kc = 0; kc < 128; kc += 32) {
#pragma unroll
        for (int l = 0; l < 4; l++) {
            int idx = tid + l * 256;
            int k = idx >> 5, j4 = idx & 31;
            int j = j4 * 4;
            float4 wv;
            if (j < 64) wv = *reinterpret_cast<const float4*>(&Wmu[(kc + k) * 64 + j]);
            else        wv = *reinterpret_cast<const float4*>(&Wls[(kc + k) * 64 + j - 64]);
            *reinterpret_cast<float4*>(&ws[k][j]) = wv;
        }
#pragma unroll
        for (int l = 0; l < 4; l++) {
            int idx = tid + l * 256;
            int r = idx >> 3, kq = idx & 7;
            float4 v = make_float4(0.f, 0.f, 0.f, 0.f);
            if (rbase + r < nrows)
                v = *reinterpret_cast<const float4*>(
                    &g_agg2[(size_t)(rbase + r) * C + kc + kq * 4]);
            xsT[kq * 4 + 0][r] = v.x;
            xsT[kq * 4 + 1][r] = v.y;
            xsT[kq * 4 + 2][r] = v.z;
            xsT[kq * 4 + 3][r] = v.w;
        }
        __syncthreads();
#pragma unroll 8
        for (int k = 0; k < 32; k++) {
            float xv[8], wv[8];
            *reinterpret_cast<float4*>(&xv[0]) = *reinterpret_cast<float4*>(&xsT[k][ty * 8]);
            *reinterpret_cast<float4*>(&xv[4]) = *reinterpret_cast<float4*>(&xsT[k][ty * 8 + 4]);
            *reinterpret_cast<float4*>(&wv[0]) = *reinterpret_cast<float4*>(&ws[k][tx * 8]);
            *reinterpret_cast<float4*>(&wv[4]) = *reinterpret_cast<float4*>(&ws[k][tx * 8 + 4]);
#pragma unroll
            for (int i = 0; i < 8; i++)
#pragma unroll
                for (int j = 0; j < 8; j++)
                    acc[i][j] = fmaf(xv[i], wv[j], acc[i][j]);
        }
        __syncthreads();
    }

    float bias[8];
    {
        const float* bp = (tx < 8) ? (bmu + tx * 8) : (bls + (tx - 8) * 8);
        *reinterpret_cast<float4*>(&bias[0]) = *reinterpret_cast<const float4*>(&bp[0]);
        *reinterpret_cast<float4*>(&bias[4]) = *reinterpret_cast<const float4*>(&bp[4]);
    }
    const size_t obase = (tx < 8) ? (size_t)0 : (size_t)NN * 64;
    const int    jo    = (tx < 8) ? tx * 8 : (tx - 8) * 8;
#pragma unroll
    for (int i = 0; i < 8; i++) {
        int r = rbase + ty * 8 + i;
        if (r < nrows) {
            float* op = out + obase + (size_t)r * 64 + jo;
            *reinterpret_cast<float4*>(op) =
                make_float4(acc[i][0] + bias[0], acc[i][1] + bias[1],
                            acc[i][2] + bias[2], acc[i][3] + bias[3]);
            *reinterpret_cast<float4*>(op + 4) =
                make_float4(acc[i][4] + bias[4], acc[i][5] + bias[5],
                            acc[i][6] + bias[6], acc[i][7] + bias[7]);
        }
    }
}

// ---------------------------------------------------------------------------
extern "C" void kernel_launch(void* const* d_in, const int* in_sizes, int n_in,
                              void* d_out, int out_size) {
    const float* x   = (const float*)d_in[0];
    const int*   ei  = (const int*)  d_in[1];
    const float* W1  = (const float*)d_in[2];
    const float* b1  = (const float*)d_in[3];
    const float* Wmu = (const float*)d_in[4];
    const float* bmu = (const float*)d_in[5];
    const float* Wls = (const float*)d_in[6];
    const float* bls = (const float*)d_in[7];
    float* out = (float*)d_out;

    const int* src = ei;        // edge_index[0]
    const int* dst = ei + NE;   // edge_index[1]

    const int gemm_blocks   = (NN + 127) / 128;
    const int gather_blocks = (NN * 32 + 255) / 256;

    zero_cnt_kernel<<<(NN + 255) / 256, 256>>>();
    count_kernel<<<(NE + 255) / 256, 256>>>(dst);
    scan1_kernel<<<NBLK_SCAN, SCAN_CHUNK>>>();
    scan2_kernel<<<1, 128>>>();
    scan3_kernel<<<NBLK_SCAN, SCAN_CHUNK>>>();
    fill_kernel<<<(NE + 255) / 256, 256>>>(src, dst);
    gemm1_kernel<<<gemm_blocks, 256>>>(x, W1, NN);
    gather_kernel<0><<<gather_blocks, 256>>>(b1);
    gather_kernel<1><<<gather_blocks, 256>>>(b1);
    gemm_final_kernel<<<gemm_blocks, 256>>>(Wmu, Wls, bmu, bls, out, NN);
}

// round 4
// speedup vs baseline: 2.6426x; 1.4320x over previous
#include <cuda_runtime.h>
#include <cstdint>

#define NN 100000
#define NE 1600000
#define C  128

#define SCAN_CHUNK 1024
#define NBLK_SCAN ((NN + SCAN_CHUNK - 1) / SCAN_CHUNK)   // 98

// ---------------------------------------------------------------------------
// Scratch (device globals — no allocation allowed)
// ---------------------------------------------------------------------------
__device__ int   g_cnt [NN];
__device__ int   g_off [NN + 1];
__device__ int   g_bsum[SCAN_CHUNK];
__device__ int   g_csrc[NE];
__device__ float g_dinv[NN];
__device__ float g_h   [(size_t)NN * C];   // x@W1
__device__ float g_hn  [(size_t)NN * C];   // normalized hidden
__device__ float g_agg2[(size_t)NN * C];   // stage-2 aggregate

__device__ __forceinline__ uint32_t f2tf32(float f) {
    uint32_t r; asm("cvt.rna.tf32.f32 %0, %1;" : "=r"(r) : "f"(f)); return r;
}

// ---------------------------------------------------------------------------
// CSR build
// ---------------------------------------------------------------------------
__global__ void zero_cnt_kernel() {
    int i = blockIdx.x * blockDim.x + threadIdx.x;
    if (i < NN) g_cnt[i] = 0;
}
__global__ void count_kernel(const int* __restrict__ dst) {
    int e = blockIdx.x * blockDim.x + threadIdx.x;
    if (e < NE) atomicAdd(&g_cnt[dst[e]], 1);
}
__global__ __launch_bounds__(SCAN_CHUNK)
void scan1_kernel() {
    __shared__ int sh[SCAN_CHUNK];
    int i = blockIdx.x * SCAN_CHUNK + threadIdx.x;
    int v = (i < NN) ? g_cnt[i] : 0;
    sh[threadIdx.x] = v;
    __syncthreads();
#pragma unroll
    for (int off = 1; off < SCAN_CHUNK; off <<= 1) {
        int t = (threadIdx.x >= off) ? sh[threadIdx.x - off] : 0;
        __syncthreads();
        sh[threadIdx.x] += t;
        __syncthreads();
    }
    if (i < NN) g_off[i] = sh[threadIdx.x] - v;
    if (threadIdx.x == SCAN_CHUNK - 1) g_bsum[blockIdx.x] = sh[SCAN_CHUNK - 1];
}
__global__ __launch_bounds__(128)
void scan2_kernel() {
    __shared__ int sh[128];
    int v = (threadIdx.x < NBLK_SCAN) ? g_bsum[threadIdx.x] : 0;
    sh[threadIdx.x] = v;
    __syncthreads();
#pragma unroll
    for (int off = 1; off < 128; off <<= 1) {
        int t = (threadIdx.x >= off) ? sh[threadIdx.x - off] : 0;
        __syncthreads();
        sh[threadIdx.x] += t;
        __syncthreads();
    }
    if (threadIdx.x < NBLK_SCAN) g_bsum[threadIdx.x] = sh[threadIdx.x] - v;
}
__global__ __launch_bounds__(SCAN_CHUNK)
void scan3_kernel() {
    int i = blockIdx.x * SCAN_CHUNK + threadIdx.x;
    if (i < NN) {
        g_off[i] += g_bsum[blockIdx.x];
        g_dinv[i] = rsqrtf((float)g_cnt[i] + 1.0f);
        g_cnt[i] = 0;
    }
    if (i == 0) g_off[NN] = NE;
}
__global__ void fill_kernel(const int* __restrict__ src, const int* __restrict__ dst) {
    int e = blockIdx.x * blockDim.x + threadIdx.x;
    if (e < NE) {
        int d = dst[e];
        int p = atomicAdd(&g_cnt[d], 1);
        g_csrc[g_off[d] + p] = src[e];
    }
}

// ---------------------------------------------------------------------------
// tf32 warp-MMA GEMM: D[128-row tile, 128] = A @ W
// MODE 0: A = X,      W = W1 [128,128],          D -> g_h
// MODE 1: A = g_agg2, W = [Wmu|Wls] (two 64-col), D -> [mu | logstd] + bias
// 8 warps: 2 (M) x 4 (N); warp tile 64x32 = 4x4 m16n8k8 tiles; K chunked by 32.
// ---------------------------------------------------------------------------
#define AS_STRIDE 36
#define BS_STRIDE 136

__device__ __forceinline__ void mma_tf32(float* c, const uint32_t* a, const uint32_t* b) {
    asm volatile(
        "mma.sync.aligned.m16n8k8.row.col.f32.tf32.tf32.f32 "
        "{%0,%1,%2,%3}, {%4,%5,%6,%7}, {%8,%9}, {%0,%1,%2,%3};"
        : "+f"(c[0]), "+f"(c[1]), "+f"(c[2]), "+f"(c[3])
        : "r"(a[0]), "r"(a[1]), "r"(a[2]), "r"(a[3]), "r"(b[0]), "r"(b[1]));
}

template <int MODE>
__global__ __launch_bounds__(256, 2)
void mma_gemm_kernel(const float* __restrict__ X,
                     const float* __restrict__ Wa, const float* __restrict__ Wb,
                     const float* __restrict__ bmu, const float* __restrict__ bls,
                     float* __restrict__ out, int nrows) {
    __shared__ float As[128 * AS_STRIDE];   // 18.0 KB
    __shared__ float Bs[32 * BS_STRIDE];    // 17.4 KB

    const int tid    = threadIdx.x;
    const int lane   = tid & 31;
    const int wid    = tid >> 5;
    const int warp_m = wid >> 2;    // 0..1 -> 64 rows each
    const int warp_n = wid & 3;     // 0..3 -> 32 cols each
    const int rbase  = blockIdx.x * 128;
    const int gid    = lane >> 2;   // group id 0..7
    const int tig    = lane & 3;    // thread-in-group 0..3

    float acc[4][4][4];
#pragma unroll
    for (int mt = 0; mt < 4; mt++)
#pragma unroll
        for (int nt = 0; nt < 4; nt++)
#pragma unroll
            for (int q = 0; q < 4; q++) acc[mt][nt][q] = 0.f;

    const float* __restrict__ Ap = (MODE == 0) ? X : g_agg2;

    for (int kc = 0; kc < 128; kc += 32) {
        // ---- A chunk: 128 rows x 32 k (coalesced float4, tf32-rounded) ----
#pragma unroll
        for (int i = 0; i < 4; i++) {
            int f   = tid + i * 256;
            int row = f >> 3;
            int c4  = (f & 7) * 4;
            float4 v = make_float4(0.f, 0.f, 0.f, 0.f);
            if (rbase + row < nrows)
                v = *reinterpret_cast<const float4*>(&Ap[(size_t)(rbase + row) * C + kc + c4]);
            uint4 w;
            w.x = f2tf32(v.x); w.y = f2tf32(v.y); w.z = f2tf32(v.z); w.w = f2tf32(v.w);
            *reinterpret_cast<uint4*>(&As[row * AS_STRIDE + c4]) = w;
        }
        // ---- B chunk: 32 k x 128 n ----
#pragma unroll
        for (int i = 0; i < 4; i++) {
            int f  = tid + i * 256;
            int k  = f >> 5;
            int n4 = (f & 31) * 4;
            float4 v;
            if (MODE == 0) {
                v = *reinterpret_cast<const float4*>(&Wa[(kc + k) * 128 + n4]);
            } else {
                v = (n4 < 64)
                    ? *reinterpret_cast<const float4*>(&Wa[(kc + k) * 64 + n4])
                    : *reinterpret_cast<const float4*>(&Wb[(kc + k) * 64 + n4 - 64]);
            }
            uint4 w;
            w.x = f2tf32(v.x); w.y = f2tf32(v.y); w.z = f2tf32(v.z); w.w = f2tf32(v.w);
            *reinterpret_cast<uint4*>(&Bs[k * BS_STRIDE + n4]) = w;
        }
        __syncthreads();

#pragma unroll
        for (int kk = 0; kk < 4; kk++) {
            const int k0 = kk * 8;
            uint32_t a[4][4], b[4][2];
#pragma unroll
            for (int mt = 0; mt < 4; mt++) {
                const float* p = &As[(warp_m * 64 + mt * 16 + gid) * AS_STRIDE + k0 + tig];
                a[mt][0] = __float_as_uint(p[0]);
                a[mt][1] = __float_as_uint(p[8 * AS_STRIDE]);
                a[mt][2] = __float_as_uint(p[4]);
                a[mt][3] = __float_as_uint(p[8 * AS_STRIDE + 4]);
            }
#pragma unroll
            for (int nt = 0; nt < 4; nt++) {
                const float* p = &Bs[(k0 + tig) * BS_STRIDE + warp_n * 32 + nt * 8 + gid];
                b[nt][0] = __float_as_uint(p[0]);
                b[nt][1] = __float_as_uint(p[4 * BS_STRIDE]);
            }
#pragma unroll
            for (int mt = 0; mt < 4; mt++)
#pragma unroll
                for (int nt = 0; nt < 4; nt++)
                    mma_tf32(acc[mt][nt], a[mt], b[nt]);
        }
        __syncthreads();
    }

    // ---- epilogue ----
#pragma unroll
    for (int mt = 0; mt < 4; mt++) {
        const int r0 = rbase + warp_m * 64 + mt * 16 + gid;
#pragma unroll
        for (int nt = 0; nt < 4; nt++) {
            const int col = warp_n * 32 + nt * 8 + tig * 2;
            if (MODE == 0) {
                if (r0 < nrows)
                    *reinterpret_cast<float2*>(&g_h[(size_t)r0 * C + col]) =
                        make_float2(acc[mt][nt][0], acc[mt][nt][1]);
                if (r0 + 8 < nrows)
                    *reinterpret_cast<float2*>(&g_h[(size_t)(r0 + 8) * C + col]) =
                        make_float2(acc[mt][nt][2], acc[mt][nt][3]);
            } else {
                const bool is_mu = (col < 64);
                const int  jo    = is_mu ? col : col - 64;
                const float* bp  = is_mu ? bmu : bls;
                float* obase     = is_mu ? out : out + (size_t)NN * 64;
                float2 bv = *reinterpret_cast<const float2*>(&bp[jo]);
                if (r0 < nrows)
                    *reinterpret_cast<float2*>(&obase[(size_t)r0 * 64 + jo]) =
                        make_float2(acc[mt][nt][0] + bv.x, acc[mt][nt][1] + bv.y);
                if (r0 + 8 < nrows)
                    *reinterpret_cast<float2*>(&obase[(size_t)(r0 + 8) * 64 + jo]) =
                        make_float2(acc[mt][nt][2] + bv.x, acc[mt][nt][3] + bv.y);
            }
        }
    }
}

// ---------------------------------------------------------------------------
// CSR gather: one warp per node, lane owns 4 channels.
// STAGE 0: H=g_h  -> bias/relu/normalize -> g_hn
// STAGE 1: H=g_hn -> g_agg2
// ---------------------------------------------------------------------------
template <int STAGE>
__global__ __launch_bounds__(256)
void gather_kernel(const float* __restrict__ b1) {
    int node = (blockIdx.x * blockDim.x + threadIdx.x) >> 5;
    int lane = threadIdx.x & 31;
    if (node >= NN) return;

    const float* __restrict__ H = (STAGE == 0) ? g_h : g_hn;
    const size_t cb = (size_t)lane * 4;
    const float dn = g_dinv[node];

    float4 hv = *reinterpret_cast<const float4*>(&H[(size_t)node * C + cb]);
    float cc = dn * dn;
    float4 acc = make_float4(hv.x * cc, hv.y * cc, hv.z * cc, hv.w * cc);

    int e   = g_off[node];
    int end = g_off[node + 1];

    for (; e + 4 <= end; e += 4) {
        int s0 = g_csrc[e + 0], s1 = g_csrc[e + 1];
        int s2 = g_csrc[e + 2], s3 = g_csrc[e + 3];
        float c0 = g_dinv[s0] * dn, c1 = g_dinv[s1] * dn;
        float c2 = g_dinv[s2] * dn, c3 = g_dinv[s3] * dn;
        float4 v0 = *reinterpret_cast<const float4*>(&H[(size_t)s0 * C + cb]);
        float4 v1 = *reinterpret_cast<const float4*>(&H[(size_t)s1 * C + cb]);
        float4 v2 = *reinterpret_cast<const float4*>(&H[(size_t)s2 * C + cb]);
        float4 v3 = *reinterpret_cast<const float4*>(&H[(size_t)s3 * C + cb]);
        acc.x = fmaf(c0, v0.x, fmaf(c1, v1.x, fmaf(c2, v2.x, fmaf(c3, v3.x, acc.x))));
        acc.y = fmaf(c0, v0.y, fmaf(c1, v1.y, fmaf(c2, v2.y, fmaf(c3, v3.y, acc.y))));
        acc.z = fmaf(c0, v0.z, fmaf(c1, v1.z, fmaf(c2, v2.z, fmaf(c3, v3.z, acc.z))));
        acc.w = fmaf(c0, v0.w, fmaf(c1, v1.w, fmaf(c2, v2.w, fmaf(c3, v3.w, acc.w))));
    }
    for (; e < end; e++) {
        int s = g_csrc[e];
        float c = g_dinv[s] * dn;
        float4 v = *reinterpret_cast<const float4*>(&H[(size_t)s * C + cb]);
        acc.x = fmaf(c, v.x, acc.x);
        acc.y = fmaf(c, v.y, acc.y);
        acc.z = fmaf(c, v.z, acc.z);
        acc.w = fmaf(c, v.w, acc.w);
    }

    if (STAGE == 0) {
        float4 bv = *reinterpret_cast<const float4*>(&b1[lane * 4]);
        acc.x = fmaxf(acc.x + bv.x, 0.f);
        acc.y = fmaxf(acc.y + bv.y, 0.f);
        acc.z = fmaxf(acc.z + bv.z, 0.f);
        acc.w = fmaxf(acc.w + bv.w, 0.f);
        float ss = acc.x * acc.x + acc.y * acc.y + acc.z * acc.z + acc.w * acc.w;
#pragma unroll
        for (int off = 16; off > 0; off >>= 1)
            ss += __shfl_xor_sync(0xffffffffu, ss, off);
        float scale = 1.0f / fmaxf(sqrtf(ss), 1e-12f);
        acc.x *= scale; acc.y *= scale; acc.z *= scale; acc.w *= scale;
        *reinterpret_cast<float4*>(&g_hn[(size_t)node * C + cb]) = acc;
    } else {
        *reinterpret_cast<float4*>(&g_agg2[(size_t)node * C + cb]) = acc;
    }
}

// ---------------------------------------------------------------------------
extern "C" void kernel_launch(void* const* d_in, const int* in_sizes, int n_in,
                              void* d_out, int out_size) {
    const float* x   = (const float*)d_in[0];
    const int*   ei  = (const int*)  d_in[1];
    const float* W1  = (const float*)d_in[2];
    const float* b1  = (const float*)d_in[3];
    const float* Wmu = (const float*)d_in[4];
    const float* bmu = (const float*)d_in[5];
    const float* Wls = (const float*)d_in[6];
    const float* bls = (const float*)d_in[7];
    float* out = (float*)d_out;

    const int* src = ei;
    const int* dst = ei + NE;

    const int mma_blocks    = (NN + 127) / 128;       // 782
    const int gather_blocks = (NN * 32 + 255) / 256;

    zero_cnt_kernel<<<(NN + 255) / 256, 256>>>();
    count_kernel<<<(NE + 255) / 256, 256>>>(dst);
    scan1_kernel<<<NBLK_SCAN, SCAN_CHUNK>>>();
    scan2_kernel<<<1, 128>>>();
    scan3_kernel<<<NBLK_SCAN, SCAN_CHUNK>>>();
    fill_kernel<<<(NE + 255) / 256, 256>>>(src, dst);
    mma_gemm_kernel<0><<<mma_blocks, 256>>>(x, W1, nullptr, nullptr, nullptr, nullptr, NN);
    gather_kernel<0><<<gather_blocks, 256>>>(b1);
    gather_kernel<1><<<gather_blocks, 256>>>(b1);
    mma_gemm_kernel<1><<<mma_blocks, 256>>>(nullptr, Wmu, Wls, bmu, bls, out, NN);
}